// round 3
// baseline (speedup 1.0000x reference)
#include <cuda_runtime.h>
#include <math.h>

#define BSZ   4096
#define TSZ   1024
#define DIN   2
#define EMD   128
#define CELL  128
#define DOUT  5
#define GATES 512   /* 4*CELL */
#define KTOT  256   /* EMD + CELL */
#define NCTA  128
#define ROWS  32    /* batch rows per CTA */
#define NTHR  256
#define AST   260   /* As row stride in floats (padded: 260%32==4 -> conflict-free y reads) */
#define WOST  132   /* WoS row stride */

/* ---------------- persistent device scratch (no allocs allowed) ---------------- */
__device__ float g_Wcat[KTOT * GATES];   /* [k][n] k-major: k<128 -> W_ih[n][k], else W_hh[n][k-128] */
__device__ float g_bias[GATES];          /* b_ih + b_hh */

/* ---------------- helpers ---------------- */
__device__ __forceinline__ unsigned long long pack2(float lo, float hi) {
    unsigned long long r;
    asm("mov.b64 %0, {%1, %2};" : "=l"(r) : "f"(lo), "f"(hi));
    return r;
}
__device__ __forceinline__ void unpack2(unsigned long long v, float &lo, float &hi) {
    asm("mov.b64 {%0, %1}, %2;" : "=f"(lo), "=f"(hi) : "l"(v));
}
/* Blackwell packed fp32 FMA: 2 FMAs per instruction */
__device__ __forceinline__ void ffma2(unsigned long long &d, unsigned long long a, unsigned long long b) {
    asm("fma.rn.f32x2 %0, %1, %2, %0;" : "+l"(d) : "l"(a), "l"(b));
}
/* accurate-enough fast transcendentals (err ~1e-6, fine over 1024-step recurrence) */
__device__ __forceinline__ float sigm(float x) {
    return __fdividef(1.0f, 1.0f + __expf(-x));
}
__device__ __forceinline__ float tanh_f(float x) {
    float e = __expf(-2.0f * fabsf(x));          /* in (0,1], no overflow */
    float r = __fdividef(1.0f - e, 1.0f + e);
    return copysignf(r, x);
}

__device__ __forceinline__ void cp16(void* s, const void* g) {
    unsigned sa = (unsigned)__cvta_generic_to_shared(s);
    asm volatile("cp.async.cg.shared.global [%0], [%1], 16;" :: "r"(sa), "l"(g));
}
__device__ __forceinline__ void cp_commit() { asm volatile("cp.async.commit_group;"); }
__device__ __forceinline__ void cp_wait0()  { asm volatile("cp.async.wait_group 0;" ::: "memory"); }

/* stage one 8-k weight chunk (16KB) into a shared buffer */
__device__ __forceinline__ void prefetch_chunk(float* Bbuf, int c, int tid) {
    const float4* src = (const float4*)(g_Wcat + c * 8 * GATES);
    float4* dst = (float4*)Bbuf;
#pragma unroll
    for (int i = 0; i < 4; i++)
        cp16(dst + tid + i * NTHR, src + tid + i * NTHR);
    cp_commit();
}

/* ---------------- setup: fuse weights/biases ---------------- */
__global__ void setup_kernel(const float* __restrict__ W_ih, const float* __restrict__ W_hh,
                             const float* __restrict__ b_ih, const float* __restrict__ b_hh) {
    int idx = blockIdx.x * blockDim.x + threadIdx.x;
    if (idx < KTOT * GATES) {
        int k = idx / GATES, n = idx % GATES;
        g_Wcat[idx] = (k < EMD) ? W_ih[n * EMD + k] : W_hh[n * CELL + (k - EMD)];
    }
    if (idx < GATES) g_bias[idx] = b_ih[idx] + b_hh[idx];
}

/* ---------------- persistent kernel: whole sequence, one launch ----------------
 * grid 128 CTAs x 256 threads. CTA owns 32 batch rows end-to-end.
 * Thread micro-tile: 8 rows x (4 gates x 2 cells); c/h live in registers.
 * smem layout (floats):
 *   As  [0     , 8320 )  A-tile [32][260] (e | h), padded
 *   Bs0 [8320  , 12416)  weight chunk buffer 0
 *   Bs1 [12416 , 16512)  weight chunk buffer 1
 *   WoS [16512 , 17172)  Wo [5][132]
 *   WeS [17172 , 17428)  We as float2 pairs
 *   beS [17428 , 17556)
 *   xs  [17556 , 17620)  x staging, float2[32]
 */
#define SMEM_FLOATS 17620

__global__ void __launch_bounds__(NTHR, 1)
lstm_persist(const float* __restrict__ inputs,
             const float* __restrict__ We,  const float* __restrict__ be,
             const float* __restrict__ Wo,  const float* __restrict__ bov,
             float* __restrict__ out) {
    extern __shared__ float smf[];
    float*  As  = smf;
    float*  Bs0 = smf + 8320;
    float*  Bs1 = smf + 12416;
    float*  WoS = smf + 16512;
    float*  WeS = smf + 17172;
    float*  beS = smf + 17428;
    float2* xs  = (float2*)(smf + 17556);

    const int tid  = threadIdx.x;
    const int row0 = blockIdx.x * ROWS;
    const int p    = tid & 63;     /* cell pair index (cells 2p, 2p+1) */
    const int rg   = tid >> 6;     /* row group: rows 8*rg .. 8*rg+7 */

    /* preload small weights into smem */
    for (int i = tid; i < DOUT * CELL; i += NTHR) WoS[(i / CELL) * WOST + (i % CELL)] = Wo[i];
    for (int i = tid; i < EMD; i += NTHR) {
        WeS[2 * i]     = We[2 * i];
        WeS[2 * i + 1] = We[2 * i + 1];
        beS[i]         = be[i];
    }
    /* zero h-part of A-tile */
    for (int i = tid; i < ROWS * CELL; i += NTHR)
        As[(i >> 7) * AST + EMD + (i & 127)] = 0.0f;

    /* per-thread gate biases, packed (accumulator init value) */
    unsigned long long bia[4];
#pragma unroll
    for (int g = 0; g < 4; g++)
        bia[g] = pack2(g_bias[g * 128 + 2 * p], g_bias[g * 128 + 2 * p + 1]);

    float c0[8], c1[8], h0r[8], h1r[8];
#pragma unroll
    for (int rr = 0; rr < 8; rr++) { c0[rr] = c1[rr] = h0r[rr] = h1r[rr] = 0.0f; }

    unsigned long long acc[8][4];
#pragma unroll
    for (int rr = 0; rr < 8; rr++)
#pragma unroll
        for (int g = 0; g < 4; g++) acc[rr][g] = bia[g];

    const float bo_r = (tid < ROWS * DOUT) ? bov[tid % DOUT] : 0.0f;

    prefetch_chunk(Bs0, 0, tid);   /* chunk 0 in flight */

    for (int t = 0; t < TSZ; t++) {
        /* stage x[row0..row0+31][t] (DIN=2 -> one float2 per row) */
        if (tid < ROWS)
            xs[tid] = ((const float2*)inputs)[(size_t)(row0 + tid) * TSZ + t];
        __syncthreads();   /* S1: xs ready; previous y-phase finished */

        /* e-phase: As[r][0..127] = relu(We @ x + be) */
#pragma unroll
        for (int it = 0; it < 16; it++) {
            int idx = tid + it * NTHR;
            int r = idx >> 7, j = idx & 127;
            float2 x = xs[r];
            float e = fmaf(WeS[2 * j], x.x, fmaf(WeS[2 * j + 1], x.y, beS[j]));
            As[r * AST + j] = fmaxf(e, 0.0f);
        }

        /* GEMM: gates[32,512] += A[32,256] @ Wcat[256,512], double-buffered weight stream */
        for (int c = 0; c < 32; c++) {
            cp_wait0();
            __syncthreads();                 /* chunk c arrived; As complete (c==0) */
            bool lastall = (t == TSZ - 1) && (c == 31);
            if (!lastall) {
                int nc = (c < 31) ? c + 1 : 0;   /* wrap: prefetch chunk 0 for next step */
                prefetch_chunk((nc & 1) ? Bs1 : Bs0, nc, tid);
            }
            const float* Bc = (c & 1) ? Bs1 : Bs0;
#pragma unroll
            for (int half = 0; half < 2; half++) {
                float a4[8][4];
#pragma unroll
                for (int rr = 0; rr < 8; rr++)
                    *(float4*)a4[rr] = *(const float4*)&As[(rg * 8 + rr) * AST + c * 8 + half * 4];
#pragma unroll
                for (int kk = 0; kk < 4; kk++) {
                    const float* brow = Bc + (half * 4 + kk) * GATES;
                    unsigned long long b0 = *(const unsigned long long*)(brow + 2 * p);
                    unsigned long long b1 = *(const unsigned long long*)(brow + 128 + 2 * p);
                    unsigned long long b2 = *(const unsigned long long*)(brow + 256 + 2 * p);
                    unsigned long long b3 = *(const unsigned long long*)(brow + 384 + 2 * p);
#pragma unroll
                    for (int rr = 0; rr < 8; rr++) {
                        unsigned long long a2 = pack2(a4[rr][kk], a4[rr][kk]);
                        ffma2(acc[rr][0], a2, b0);
                        ffma2(acc[rr][1], a2, b1);
                        ffma2(acc[rr][2], a2, b2);
                        ffma2(acc[rr][3], a2, b3);
                    }
                }
            }
        }

        /* LSTM pointwise — all 4 gates of cells 2p,2p+1 are in this thread */
#pragma unroll
        for (int rr = 0; rr < 8; rr++) {
            float gi0, gi1, gf0, gf1, gg0, gg1, go0, go1;
            unpack2(acc[rr][0], gi0, gi1);
            unpack2(acc[rr][1], gf0, gf1);
            unpack2(acc[rr][2], gg0, gg1);
            unpack2(acc[rr][3], go0, go1);
            {
                float iv = sigm(gi0), fv = sigm(gf0), gv = tanh_f(gg0), ov = sigm(go0);
                c0[rr]  = fmaf(fv, c0[rr], iv * gv);
                h0r[rr] = ov * tanh_f(c0[rr]);
            }
            {
                float iv = sigm(gi1), fv = sigm(gf1), gv = tanh_f(gg1), ov = sigm(go1);
                c1[rr]  = fmaf(fv, c1[rr], iv * gv);
                h1r[rr] = ov * tanh_f(c1[rr]);
            }
            acc[rr][0] = bia[0]; acc[rr][1] = bia[1];
            acc[rr][2] = bia[2]; acc[rr][3] = bia[3];
            int r = rg * 8 + rr;
            *(float2*)&As[r * AST + EMD + 2 * p] = make_float2(h0r[rr], h1r[rr]);
        }
        __syncthreads();   /* S2: h_new visible in As */

        /* output MLP: y[32,5] = h_new @ Wo^T + bo */
        if (tid < ROWS * DOUT) {
            int r = tid / DOUT, d = tid % DOUT;
            float s = bo_r;
            const float* hrow = As + r * AST + EMD;
            const float* wrow = WoS + d * WOST;
#pragma unroll 16
            for (int j = 0; j < CELL; j++) s = fmaf(hrow[j], wrow[j], s);
            out[((size_t)(row0 + r) * TSZ + t) * DOUT + d] = s;
        }
        /* next S1 orders y-phase before e-part overwrite */
    }

    /* tail: final h, c straight from registers */
    size_t base = (size_t)BSZ * TSZ * DOUT;
#pragma unroll
    for (int rr = 0; rr < 8; rr++) {
        int grow = row0 + rg * 8 + rr;
        *(float2*)&out[base + (size_t)grow * CELL + 2 * p] =
            make_float2(h0r[rr], h1r[rr]);
        *(float2*)&out[base + (size_t)BSZ * CELL + (size_t)grow * CELL + 2 * p] =
            make_float2(c0[rr], c1[rr]);
    }
}

/* ---------------- launch: 2 graph nodes only ---------------- */
extern "C" void kernel_launch(void* const* d_in, const int* in_sizes, int n_in,
                              void* d_out, int out_size) {
    const float* inputs = (const float*)d_in[0];
    const float* We     = (const float*)d_in[1];
    const float* be     = (const float*)d_in[2];
    const float* W_ih   = (const float*)d_in[3];
    const float* W_hh   = (const float*)d_in[4];
    const float* b_ih   = (const float*)d_in[5];
    const float* b_hh   = (const float*)d_in[6];
    const float* Wo     = (const float*)d_in[7];
    const float* bo     = (const float*)d_in[8];
    float* out = (float*)d_out;

    static int smem_set = 0;
    if (!smem_set) {
        cudaFuncSetAttribute(lstm_persist, cudaFuncAttributeMaxDynamicSharedMemorySize,
                             SMEM_FLOATS * (int)sizeof(float));
        smem_set = 1;
    }

    setup_kernel<<<(KTOT * GATES + 255) / 256, 256>>>(W_ih, W_hh, b_ih, b_hh);
    lstm_persist<<<NCTA, NTHR, SMEM_FLOATS * sizeof(float)>>>(inputs, We, be, Wo, bo, out);
}

// round 4
// speedup vs baseline: 1.0600x; 1.0600x over previous
#include <cuda_runtime.h>
#include <math.h>

#define BSZ   4096
#define TSZ   1024
#define DIN   2
#define EMD   128
#define CELL  128
#define DOUT  5
#define GATES 512   /* 4*CELL */
#define KTOT  256   /* EMD + CELL */
#define NCTA  128
#define ROWS  32    /* batch rows per CTA */
#define NTHR  256
#define AST   260   /* As row stride in floats (padded: 260%32==4 -> conflict-free y reads) */
#define WOST  132   /* WoS row stride */

/* ---------------- persistent device scratch (no allocs allowed) ---------------- */
__device__ float g_Wcat[KTOT * GATES];   /* [k][n] k-major: k<128 -> W_ih[n][k], else W_hh[n][k-128] */
__device__ float g_bias[GATES];          /* b_ih + b_hh */

/* ---------------- helpers ---------------- */
__device__ __forceinline__ unsigned long long pack2(float lo, float hi) {
    unsigned long long r;
    asm("mov.b64 %0, {%1, %2};" : "=l"(r) : "f"(lo), "f"(hi));
    return r;
}
__device__ __forceinline__ void unpack2(unsigned long long v, float &lo, float &hi) {
    asm("mov.b64 {%0, %1}, %2;" : "=f"(lo), "=f"(hi) : "l"(v));
}
/* Blackwell packed fp32 FMA: 2 FMAs per instruction */
__device__ __forceinline__ void ffma2(unsigned long long &d, unsigned long long a, unsigned long long b) {
    asm("fma.rn.f32x2 %0, %1, %2, %0;" : "+l"(d) : "l"(a), "l"(b));
}
/* accurate-enough fast transcendentals (err ~1e-6, fine over 1024-step recurrence) */
__device__ __forceinline__ float sigm(float x) {
    return __fdividef(1.0f, 1.0f + __expf(-x));
}
__device__ __forceinline__ float tanh_f(float x) {
    float e = __expf(-2.0f * fabsf(x));          /* in (0,1], no overflow */
    float r = __fdividef(1.0f - e, 1.0f + e);
    return copysignf(r, x);
}

__device__ __forceinline__ void cp16(void* s, const void* g) {
    unsigned sa = (unsigned)__cvta_generic_to_shared(s);
    asm volatile("cp.async.cg.shared.global [%0], [%1], 16;" :: "r"(sa), "l"(g));
}
__device__ __forceinline__ void cp_commit() { asm volatile("cp.async.commit_group;"); }
__device__ __forceinline__ void cp_wait0()  { asm volatile("cp.async.wait_group 0;" ::: "memory"); }

/* stage one 8-k weight chunk (16KB) into a shared buffer */
__device__ __forceinline__ void prefetch_chunk(float* Bbuf, int c, int tid) {
    const float4* src = (const float4*)(g_Wcat + c * 8 * GATES);
    float4* dst = (float4*)Bbuf;
#pragma unroll
    for (int i = 0; i < 4; i++)
        cp16(dst + tid + i * NTHR, src + tid + i * NTHR);
    cp_commit();
}

/* ---------------- setup: fuse weights/biases ---------------- */
__global__ void setup_kernel(const float* __restrict__ W_ih, const float* __restrict__ W_hh,
                             const float* __restrict__ b_ih, const float* __restrict__ b_hh) {
    int idx = blockIdx.x * blockDim.x + threadIdx.x;
    if (idx < KTOT * GATES) {
        int k = idx / GATES, n = idx % GATES;
        g_Wcat[idx] = (k < EMD) ? W_ih[n * EMD + k] : W_hh[n * CELL + (k - EMD)];
    }
    if (idx < GATES) g_bias[idx] = b_ih[idx] + b_hh[idx];
}

/* ---------------- persistent kernel: whole sequence, one launch ----------------
 * grid 128 CTAs x 256 threads. CTA owns 32 batch rows end-to-end.
 * Thread micro-tile: 8 rows x (4 gates x 2 cells); c/h live in registers.
 * smem layout (floats):
 *   As  [0     , 8320 )  A-tile [32][260] (e | h), padded
 *   Bs0 [8320  , 12416)  weight chunk buffer 0
 *   Bs1 [12416 , 16512)  weight chunk buffer 1
 *   WoS [16512 , 17172)  Wo [5][132]
 *   WeS [17172 , 17428)  We as float2 pairs
 *   beS [17428 , 17556)
 *   xs  [17556 , 17620)  x staging, float2[32]
 */
#define SMEM_FLOATS 17620

__global__ void __launch_bounds__(NTHR, 1)
lstm_persist(const float* __restrict__ inputs,
             const float* __restrict__ We,  const float* __restrict__ be,
             const float* __restrict__ Wo,  const float* __restrict__ bov,
             float* __restrict__ out) {
    extern __shared__ float smf[];
    float*  As  = smf;
    float*  Bs0 = smf + 8320;
    float*  Bs1 = smf + 12416;
    float*  WoS = smf + 16512;
    float*  WeS = smf + 17172;
    float*  beS = smf + 17428;
    float2* xs  = (float2*)(smf + 17556);

    const int tid  = threadIdx.x;
    const int row0 = blockIdx.x * ROWS;
    const int p    = tid & 63;     /* cell pair index (cells 2p, 2p+1) */
    const int rg   = tid >> 6;     /* row group: rows 8*rg .. 8*rg+7 */

    /* preload small weights into smem */
    for (int i = tid; i < DOUT * CELL; i += NTHR) WoS[(i / CELL) * WOST + (i % CELL)] = Wo[i];
    for (int i = tid; i < EMD; i += NTHR) {
        WeS[2 * i]     = We[2 * i];
        WeS[2 * i + 1] = We[2 * i + 1];
        beS[i]         = be[i];
    }
    /* zero h-part of A-tile */
    for (int i = tid; i < ROWS * CELL; i += NTHR)
        As[(i >> 7) * AST + EMD + (i & 127)] = 0.0f;

    /* per-thread gate biases, packed (accumulator init value) */
    unsigned long long bia[4];
#pragma unroll
    for (int g = 0; g < 4; g++)
        bia[g] = pack2(g_bias[g * 128 + 2 * p], g_bias[g * 128 + 2 * p + 1]);

    float c0[8], c1[8], h0r[8], h1r[8];
#pragma unroll
    for (int rr = 0; rr < 8; rr++) { c0[rr] = c1[rr] = h0r[rr] = h1r[rr] = 0.0f; }

    unsigned long long acc[8][4];
#pragma unroll
    for (int rr = 0; rr < 8; rr++)
#pragma unroll
        for (int g = 0; g < 4; g++) acc[rr][g] = bia[g];

    const float bo_r = (tid < ROWS * DOUT) ? bov[tid % DOUT] : 0.0f;

    prefetch_chunk(Bs0, 0, tid);   /* chunk 0 in flight */

    for (int t = 0; t < TSZ; t++) {
        /* stage x[row0..row0+31][t] (DIN=2 -> one float2 per row) */
        if (tid < ROWS)
            xs[tid] = ((const float2*)inputs)[(size_t)(row0 + tid) * TSZ + t];
        __syncthreads();   /* S1: xs ready; previous y-phase finished */

        /* e-phase: As[r][0..127] = relu(We @ x + be) */
#pragma unroll
        for (int it = 0; it < 16; it++) {
            int idx = tid + it * NTHR;
            int r = idx >> 7, j = idx & 127;
            float2 x = xs[r];
            float e = fmaf(WeS[2 * j], x.x, fmaf(WeS[2 * j + 1], x.y, beS[j]));
            As[r * AST + j] = fmaxf(e, 0.0f);
        }

        /* GEMM: gates[32,512] += A[32,256] @ Wcat[256,512], double-buffered weight stream */
        for (int c = 0; c < 32; c++) {
            cp_wait0();
            __syncthreads();                 /* chunk c arrived; As complete (c==0) */
            bool lastall = (t == TSZ - 1) && (c == 31);
            if (!lastall) {
                int nc = (c < 31) ? c + 1 : 0;   /* wrap: prefetch chunk 0 for next step */
                prefetch_chunk((nc & 1) ? Bs1 : Bs0, nc, tid);
            }
            const float* Bc = (c & 1) ? Bs1 : Bs0;
#pragma unroll
            for (int half = 0; half < 2; half++) {
                float a4[8][4];
#pragma unroll
                for (int rr = 0; rr < 8; rr++)
                    *(float4*)a4[rr] = *(const float4*)&As[(rg * 8 + rr) * AST + c * 8 + half * 4];
#pragma unroll
                for (int kk = 0; kk < 4; kk++) {
                    const float* brow = Bc + (half * 4 + kk) * GATES;
                    unsigned long long b0 = *(const unsigned long long*)(brow + 2 * p);
                    unsigned long long b1 = *(const unsigned long long*)(brow + 128 + 2 * p);
                    unsigned long long b2 = *(const unsigned long long*)(brow + 256 + 2 * p);
                    unsigned long long b3 = *(const unsigned long long*)(brow + 384 + 2 * p);
#pragma unroll
                    for (int rr = 0; rr < 8; rr++) {
                        unsigned long long a2 = pack2(a4[rr][kk], a4[rr][kk]);
                        ffma2(acc[rr][0], a2, b0);
                        ffma2(acc[rr][1], a2, b1);
                        ffma2(acc[rr][2], a2, b2);
                        ffma2(acc[rr][3], a2, b3);
                    }
                }
            }
        }

        /* LSTM pointwise — all 4 gates of cells 2p,2p+1 are in this thread */
#pragma unroll
        for (int rr = 0; rr < 8; rr++) {
            float gi0, gi1, gf0, gf1, gg0, gg1, go0, go1;
            unpack2(acc[rr][0], gi0, gi1);
            unpack2(acc[rr][1], gf0, gf1);
            unpack2(acc[rr][2], gg0, gg1);
            unpack2(acc[rr][3], go0, go1);
            {
                float iv = sigm(gi0), fv = sigm(gf0), gv = tanh_f(gg0), ov = sigm(go0);
                c0[rr]  = fmaf(fv, c0[rr], iv * gv);
                h0r[rr] = ov * tanh_f(c0[rr]);
            }
            {
                float iv = sigm(gi1), fv = sigm(gf1), gv = tanh_f(gg1), ov = sigm(go1);
                c1[rr]  = fmaf(fv, c1[rr], iv * gv);
                h1r[rr] = ov * tanh_f(c1[rr]);
            }
            acc[rr][0] = bia[0]; acc[rr][1] = bia[1];
            acc[rr][2] = bia[2]; acc[rr][3] = bia[3];
            int r = rg * 8 + rr;
            *(float2*)&As[r * AST + EMD + 2 * p] = make_float2(h0r[rr], h1r[rr]);
        }
        __syncthreads();   /* S2: h_new visible in As */

        /* output MLP: y[32,5] = h_new @ Wo^T + bo */
        if (tid < ROWS * DOUT) {
            int r = tid / DOUT, d = tid % DOUT;
            float s = bo_r;
            const float* hrow = As + r * AST + EMD;
            const float* wrow = WoS + d * WOST;
#pragma unroll 16
            for (int j = 0; j < CELL; j++) s = fmaf(hrow[j], wrow[j], s);
            out[((size_t)(row0 + r) * TSZ + t) * DOUT + d] = s;
        }
        /* next S1 orders y-phase before e-part overwrite */
    }

    /* tail: final h, c straight from registers */
    size_t base = (size_t)BSZ * TSZ * DOUT;
#pragma unroll
    for (int rr = 0; rr < 8; rr++) {
        int grow = row0 + rg * 8 + rr;
        *(float2*)&out[base + (size_t)grow * CELL + 2 * p] =
            make_float2(h0r[rr], h1r[rr]);
        *(float2*)&out[base + (size_t)BSZ * CELL + (size_t)grow * CELL + 2 * p] =
            make_float2(c0[rr], c1[rr]);
    }
}

/* ---------------- launch: 2 graph nodes only ---------------- */
extern "C" void kernel_launch(void* const* d_in, const int* in_sizes, int n_in,
                              void* d_out, int out_size) {
    const float* inputs = (const float*)d_in[0];
    const float* We     = (const float*)d_in[1];
    const float* be     = (const float*)d_in[2];
    const float* W_ih   = (const float*)d_in[3];
    const float* W_hh   = (const float*)d_in[4];
    const float* b_ih   = (const float*)d_in[5];
    const float* b_hh   = (const float*)d_in[6];
    const float* Wo     = (const float*)d_in[7];
    const float* bo     = (const float*)d_in[8];
    float* out = (float*)d_out;

    static int smem_set = 0;
    if (!smem_set) {
        cudaFuncSetAttribute(lstm_persist, cudaFuncAttributeMaxDynamicSharedMemorySize,
                             SMEM_FLOATS * (int)sizeof(float));
        smem_set = 1;
    }

    setup_kernel<<<(KTOT * GATES + 255) / 256, 256>>>(W_ih, W_hh, b_ih, b_hh);
    lstm_persist<<<NCTA, NTHR, SMEM_FLOATS * sizeof(float)>>>(inputs, We, be, Wo, bo, out);
}